// round 14
// baseline (speedup 1.0000x reference)
#include <cuda_runtime.h>
#include <math.h>
#include <stdint.h>

#define HW      65536
#define HW4     16384
#define NA      9
#define NC      80
#define NTOT    (HW * NA)          // 589824
#define TOPK    1000
#define CONF    0.05f
#define NMST    0.6f
#define CTRC    32.0f
#define EXPC    18.420680743952367f   // log(1e8) -> f32
#define SCLC    4.1351665567423560f   // log(1000/16) -> f32
#define IMGF    2048.0f
#define CAP     4096

// ---------------- device scratch (no allocations allowed) ----------------
__device__ float              g_z[NTOT];          // fast logit (binning only)
__device__ float              g_m[NTOT];          // exact class max per anchor
__device__ unsigned int       g_hist[65536];
__device__ unsigned int       g_cnt;
__device__ int                g_bin;
__device__ unsigned int       g_candidx[CAP];     // stage-1: flat anchor idx
__device__ unsigned int       g_mask[1024 * 32];

// monotone float -> uint mapping (total order incl. negatives)
__device__ __forceinline__ unsigned int fmap(float f) {
    unsigned int b = __float_as_uint(f);
    return b ^ ((b & 0x80000000u) ? 0xFFFFFFFFu : 0x80000000u);
}

// =================== glibc (ARM optimized-routines) expf ===================
__constant__ unsigned long long EXP2F_TAB[32] = {
0x3ff0000000000000ULL, 0x3fefd9b0d3158574ULL, 0x3fefb5586cf9890fULL, 0x3fef9301d0125b51ULL,
0x3fef72b83c7d517bULL, 0x3fef54873168b9aaULL, 0x3fef387a6e756238ULL, 0x3fef1e9df51fdee1ULL,
0x3fef06fe0a31b715ULL, 0x3feef1a7373aa9cbULL, 0x3feedea64c123422ULL, 0x3feece086061892dULL,
0x3feebfdad5362a27ULL, 0x3feeb42b569d4f82ULL, 0x3feeab07dd485429ULL, 0x3feea47eb03a5585ULL,
0x3feea09e667f3bcdULL, 0x3fee9f75e8ec5f74ULL, 0x3feea11473eb0187ULL, 0x3feea589994cce13ULL,
0x3feeace5422aa0dbULL, 0x3feeb737b0cdc5e5ULL, 0x3feec49182a3f090ULL, 0x3feed503b23e255dULL,
0x3feee89f995ad3adULL, 0x3feeff76f2fb5e47ULL, 0x3fef199bdd85529cULL, 0x3fef3720dcef9069ULL,
0x3fef5818dcfba487ULL, 0x3fef7c97337b9b5fULL, 0x3fefa4afa2a490daULL, 0x3fefd0765b6e4540ULL };

__device__ __forceinline__ float glibc_expf(float x) {
    const double InvLn2N = 0x1.71547652b82fep+0 * 32.0;
    const double C0 = 0x1.c6af84b912394p-5 / 32.0 / 32.0 / 32.0;
    const double C1 = 0x1.ebfce50fac4f3p-3 / 32.0 / 32.0;
    const double C2 = 0x1.62e42ff0c52d6p-1 / 32.0;
    double xd = (double)x;
    double z  = InvLn2N * xd;
    double kd = nearbyint(z);
    long long ki = (long long)kd;
    double r  = z - kd;
    unsigned long long t = EXP2F_TAB[(int)(ki & 31)] + ((unsigned long long)ki << 47);
    double s  = __longlong_as_double((long long)t);
    double z2 = fma(C0, r, C1);
    double r2 = r * r;
    double y  = fma(C2, r, 1.0);
    y = fma(z2, r2, y);
    y = y * s;
    return (float)y;
}

// =================== glibc (ARM optimized-routines) logf ===================
__constant__ double LOGF_TAB[16][2] = {
 { 0x1.661ec79f8f3bep+0, -0x1.57bf7808caadep-2 },
 { 0x1.571ed4aaf883dp+0, -0x1.2bef0a7c06ddbp-2 },
 { 0x1.49539f0f010bp+0,  -0x1.01eae7f513a67p-2 },
 { 0x1.3c995b0b80385p+0, -0x1.b31d8a68224e9p-3 },
 { 0x1.30d190c8864a5p+0, -0x1.6574f0ac07758p-3 },
 { 0x1.25e227b0b8eap+0,  -0x1.1aa2bc79c81p-3  },
 { 0x1.1bb4a4a1a343fp+0, -0x1.a4e76ce8c0e5ep-4 },
 { 0x1.12358f08ae5bap+0, -0x1.1973c5a611cccp-4 },
 { 0x1.0953f419900a7p+0, -0x1.252f438e10c1ep-5 },
 { 0x1p+0,                0x0p+0              },
 { 0x1.e608cfd9a47acp-1,  0x1.aa5aa5df25984p-5 },
 { 0x1.ca4b31f026aap-1,   0x1.c5e53aa362eb4p-4 },
 { 0x1.b2036576afce6p-1,  0x1.526e57720db08p-3 },
 { 0x1.9c2d163a1aa2dp-1,  0x1.bc2860d224770p-3 },
 { 0x1.886e6037841edp-1,  0x1.1058bc8a07ee1p-2 },
 { 0x1.767dcf5534862p-1,  0x1.4043057b6ee09p-2 } };

__device__ __forceinline__ float glibc_logf(float x) {
    const double Ln2 = 0x1.62e42fefa39efp-1;
    const double A0 = -0x1.00ea348b88334p-2;
    const double A1 =  0x1.5575b0be00b6ap-2;
    const double A2 = -0x1.ffffef20a4123p-2;
    unsigned int ix = __float_as_uint(x);
    if (ix == 0x3f800000u) return 0.0f;
    unsigned int tmp = ix - 0x3f330000u;
    int i = (int)((tmp >> 19) & 15u);
    int k = (int)tmp >> 23;
    unsigned int iz = ix - (tmp & 0xff800000u);
    double invc = LOGF_TAB[i][0];
    double logc = LOGF_TAB[i][1];
    double z  = (double)__uint_as_float(iz);
    double r  = fma(z, invc, -1.0);
    double y0 = fma((double)k, Ln2, logc);
    double r2 = r * r;
    double y  = fma(A1, r, A2);
    y = fma(A0, r2, y);
    y = fma(y, r2, y0 + r);
    return (float)y;
}

// exact reference z: (m+o) - log(((1 + e^min(m,C)) + e^min(o,C)))
__device__ __forceinline__ float exact_z(float m, float o) {
    float e1 = glibc_expf(fminf(m, EXPC));
    float e2 = glibc_expf(fminf(o, EXPC));
    float L  = glibc_logf(__fadd_rn(__fadd_rn(1.0f, e1), e2));
    return __fsub_rn(__fadd_rn(m, o), L);
}
// exact reference sigmoid: 1 / (1 + exp(-z))
__device__ __forceinline__ float exact_sig(float z) {
    float e = glibc_expf(__fsub_rn(0.0f, z));
    return __fdiv_rn(1.0f, __fadd_rn(1.0f, e));
}

// fast libdevice z (binning only; within a few ulps of exact)
__device__ __forceinline__ float fast_z(float m, float o) {
    return (m + o) - logf((1.0f + expf(fminf(m, EXPC))) + expf(fminf(o, EXPC)));
}

__device__ __forceinline__ float4 max4(float4 a, float4 b) {
    return make_float4(fmaxf(a.x, b.x), fmaxf(a.y, b.y),
                       fmaxf(a.z, b.z), fmaxf(a.w, b.w));
}

// ---------------- K0: zero histogram + counter ----------------
__global__ void k_zero() {
    int t = blockIdx.x * blockDim.x + threadIdx.x;
    if (t < 65536) g_hist[t] = 0u;
    if (t == 0) g_cnt = 0u;
}

// ---------------- K1: warp-per-class-row, register-batched (R12 best) ---
__global__ __launch_bounds__(256, 4) void k_score(const float* __restrict__ obj,
                                                  const float4* __restrict__ cls4) {
    __shared__ float part[8][128];
    int lane = threadIdx.x & 31;
    int w    = threadIdx.x >> 5;
    int G0   = blockIdx.x << 5;              // first float4-group of tile
    int G    = G0 + lane;
    int a    = G0 >> 14;                     // anchor (uniform in block)
    int q    = G & (HW4 - 1);

    const float4* base = cls4 + (((size_t)(a * NC + w)) << 14) + q;
    float4 v[10];
#pragma unroll
    for (int cc = 0; cc < 10; cc++)          // pure load loop: 10 indep LDG.128
        v[cc] = base[(size_t)(cc * 8) << 14];
    float4 m01 = max4(v[0], v[1]);
    float4 m23 = max4(v[2], v[3]);
    float4 m45 = max4(v[4], v[5]);
    float4 m67 = max4(v[6], v[7]);
    float4 m89 = max4(v[8], v[9]);
    float4 m4 = max4(max4(max4(m01, m23), max4(m45, m67)), m89);
    ((float4*)part[w])[lane] = m4;
    __syncthreads();
    if (threadIdx.x < 128) {
        int p = threadIdx.x;                 // pixel within tile
        float m = part[0][p];
#pragma unroll
        for (int r = 1; r < 8; r++) m = fmaxf(m, part[r][p]);
        int gidx = (G0 << 2) + p;            // global anchor index
        float o = obj[gidx];
        float z = fast_z(m, o);
        g_z[gidx] = z;
        g_m[gidx] = m;
        atomicAdd(&g_hist[fmap(z) >> 16], 1u);
    }
}

// ---------------- K2: threshold bin via parallel block scan -------------
__global__ void k_scan() {
    __shared__ unsigned int sS[1024];
    __shared__ unsigned int sP[1024];
    __shared__ unsigned int sWarp[32];
    __shared__ unsigned int sH[64];
    int tid = threadIdx.x;
    int lane = tid & 31, wid = tid >> 5;

    unsigned int s = 0;
#pragma unroll 8
    for (int b = 0; b < 64; b++) s += g_hist[tid * 64 + b];
    sS[tid] = s;

    unsigned int p = s;
#pragma unroll
    for (int d = 1; d < 32; d <<= 1) {
        unsigned int v = __shfl_up_sync(0xffffffffu, p, d);
        if (lane >= d) p += v;
    }
    if (lane == 31) sWarp[wid] = p;
    __syncthreads();
    if (tid < 32) {
        unsigned int w = sWarp[tid];
#pragma unroll
        for (int d = 1; d < 32; d <<= 1) {
            unsigned int v = __shfl_up_sync(0xffffffffu, w, d);
            if (tid >= d) w += v;
        }
        sWarp[tid] = w;
    }
    __syncthreads();
    unsigned int P = p + (wid ? sWarp[wid - 1] : 0u);
    sP[tid] = P;
    __syncthreads();
    unsigned int T = sP[1023];
    unsigned int suff = T - P + s;
    int n = __syncthreads_count(suff >= TOPK);
    int C = n - 1;
    if (tid < 64) sH[tid] = g_hist[C * 64 + tid];
    __syncthreads();
    if (tid == 0) {
        unsigned int acc = T - sP[C];
        int bin = C * 64;
        for (int b = 63; b >= 0; b--) {
            acc += sH[b];
            if (acc >= TOPK) { bin = C * 64 + b; break; }
        }
        g_bin = bin;
    }
}

// ---------------- K3: collect candidate indices (no math) ---------------
__global__ void k_collect() {
    int t4 = blockIdx.x * blockDim.x + threadIdx.x;   // [0, NTOT/4)
    float4 z4 = ((const float4*)g_z)[t4];
    int binm1 = g_bin - 1;
    bool c0 = (int)(fmap(z4.x) >> 16) >= binm1;
    bool c1 = (int)(fmap(z4.y) >> 16) >= binm1;
    bool c2 = (int)(fmap(z4.z) >> 16) >= binm1;
    bool c3 = (int)(fmap(z4.w) >> 16) >= binm1;
    if (!(c0 | c1 | c2 | c3)) return;
#pragma unroll
    for (int k = 0; k < 4; k++) {
        bool c = (k == 0) ? c0 : (k == 1) ? c1 : (k == 2) ? c2 : c3;
        if (!c) continue;
        unsigned int p = atomicAdd(&g_cnt, 1u);
        if (p < CAP) g_candidx[p] = (unsigned int)(t4 * 4 + k);
    }
}

// ---------------- K4: FUSED tail: sort + decode + mask + nms ------------
__global__ __launch_bounds__(1024) void k_tail(const float* __restrict__ obj,
                                               const float* __restrict__ cls,
                                               const float* __restrict__ reg,
                                               const float* __restrict__ anc,
                                               float* __restrict__ out) {
    __shared__ __align__(16) unsigned long long sk[CAP];   // 32KB, reused
    int tid = threadIdx.x;
    int lane = tid & 31, wid = tid >> 5;

    // ---------- Phase 1: exact keys + bitonic sort ----------
    unsigned int c = g_cnt;
    if (c > CAP) c = CAP;
    int S = 1024;
    while (S < (int)c) S <<= 1;               // smallest pow2 >= cnt (>=1024)
    for (int i = tid; i < S; i += 1024) {
        unsigned long long key = 0ULL;
        if (i < (int)c) {
            int t = (int)g_candidx[i];
            float m = g_m[t];
            float o = obj[t];
            float s = exact_sig(exact_z(m, o));   // bit-matched to reference
            unsigned int sb = __float_as_uint(s);
            int a = t >> 16;
            int pix = t & (HW - 1);
            unsigned int n = (unsigned int)(pix * NA + a);
            // higher s first; equal s -> lower index first (JAX top_k)
            key = ((unsigned long long)sb << 32) | (unsigned long long)(~n);
        }
        sk[i] = key;
    }
    __syncthreads();
    for (int k = 2; k <= S; k <<= 1) {
        for (int j = k >> 1; j > 0; j >>= 1) {
            for (int i = tid; i < S; i += 1024) {
                int ixj = i ^ j;
                if (ixj > i) {
                    unsigned long long A = sk[i], B = sk[ixj];
                    bool dsc = ((i & k) == 0);
                    if (dsc ? (A < B) : (A > B)) { sk[i] = B; sk[ixj] = A; }
                }
            }
            __syncthreads();
        }
    }
    int myidx = -1;
    if (tid < TOPK) {
        unsigned long long key = sk[tid];
        out[tid] = __uint_as_float((unsigned int)(key >> 32));   // scores
        myidx = (int)(~(unsigned int)key);
    }
    __syncthreads();
    // reuse sk memory: [0,4000) idx | [4096,8096) lab | [8192,24192) box
    int*    s_idx = (int*)sk;
    int*    s_lab = (int*)((char*)sk + 4096);
    float4* s_box = (float4*)((char*)sk + 8192);
    if (tid < TOPK) s_idx[tid] = myidx;
    __syncthreads();

    // ---------- Phase 2: decode (warp per candidate) ----------
    for (int cand = wid; cand < TOPK; cand += 32) {
        int n = s_idx[cand];
        int pix = n / NA;
        int a = n - pix * NA;
        const float* cp = cls + ((size_t)(a * NC) << 16) + pix;
        float m = -3.4e38f;
        int lbl = NC;
        for (int cc = lane; cc < NC; cc += 32) {
            float v = cp[(size_t)cc << 16];
            if (v > m) { m = v; lbl = cc; }   // per-lane first occurrence
        }
#pragma unroll
        for (int d = 16; d; d >>= 1) {
            float vm = __shfl_down_sync(0xffffffffu, m, d);
            int vl = __shfl_down_sync(0xffffffffu, lbl, d);
            if (vm > m || (vm == m && vl < lbl)) { m = vm; lbl = vl; }
        }
        if (lane == 0) {
            const float* rp = reg + ((size_t)(a * 4) << 16) + pix;
            float r0 = rp[0];
            float r1 = rp[(size_t)1 << 16];
            float r2 = rp[(size_t)2 << 16];
            float r3 = rp[(size_t)3 << 16];
            float ax = anc[n * 4 + 0], ay = anc[n * 4 + 1];
            float aw = anc[n * 4 + 2], ah = anc[n * 4 + 3];
            float ox = fminf(fmaxf(__fmul_rn(r0, aw), -CTRC), CTRC);
            float oy = fminf(fmaxf(__fmul_rn(r1, ah), -CTRC), CTRC);
            float cx = __fadd_rn(ax, ox);
            float cy = __fadd_rn(ay, oy);
            float w = __fmul_rn(aw, glibc_expf(fminf(r2, SCLC)));
            float h = __fmul_rn(ah, glibc_expf(fminf(r3, SCLC)));
            float hw = __fmul_rn(0.5f, w);
            float hh = __fmul_rn(0.5f, h);
            float x1 = fminf(fmaxf(__fdiv_rn(__fsub_rn(cx, hw), IMGF), 0.0f), 1.0f);
            float y1 = fminf(fmaxf(__fdiv_rn(__fsub_rn(cy, hh), IMGF), 0.0f), 1.0f);
            float x2 = fminf(fmaxf(__fdiv_rn(__fadd_rn(cx, hw), IMGF), 0.0f), 1.0f);
            float y2 = fminf(fmaxf(__fdiv_rn(__fadd_rn(cy, hh), IMGF), 0.0f), 1.0f);
            out[1000 + cand] = (float)lbl;                 // labels
            out[2000 + cand * 4 + 0] = x1;                 // boxes
            out[2000 + cand * 4 + 1] = y1;
            out[2000 + cand * 4 + 2] = x2;
            out[2000 + cand * 4 + 3] = y2;
            s_lab[cand] = lbl;
            s_box[cand] = make_float4(x1, y1, x2, y2);
        }
    }
    __syncthreads();

    // ---------- Phase 3: suppression bitmask (warp per row) ----------
    for (int i = wid; i < TOPK; i += 32) {
        float4 bi = s_box[i];
        int li = s_lab[i];
        float areai = __fmul_rn(__fsub_rn(bi.z, bi.x), __fsub_rn(bi.w, bi.y));
        for (int w32 = 0; w32 < 32; w32++) {
            int j = (w32 << 5) + lane;
            bool sup = false;
            if (j < TOPK && j > i) {
                if (s_lab[j] == li) {
                    float4 bj = s_box[j];
                    float xx1 = fmaxf(bi.x, bj.x);
                    float yy1 = fmaxf(bi.y, bj.y);
                    float xx2 = fminf(bi.z, bj.z);
                    float yy2 = fminf(bi.w, bj.w);
                    float inter = __fmul_rn(fmaxf(1e-28f, __fsub_rn(xx2, xx1)),
                                            fmaxf(1e-28f, __fsub_rn(yy2, yy1)));
                    float areaj = __fmul_rn(__fsub_rn(bj.z, bj.x), __fsub_rn(bj.w, bj.y));
                    float denom = __fadd_rn(__fsub_rn(__fadd_rn(areai, areaj), inter), 1e-14f);
                    float iou = __fdiv_rn(inter, denom);
                    sup = iou > NMST;
                }
            }
            unsigned int b = __ballot_sync(0xffffffffu, sup);
            if (lane == 0) g_mask[i * 32 + w32] = b;
        }
    }
    __syncthreads();

    // ---------- Phase 4: chunked greedy scan (warp 0) ----------
    if (tid < 32) {
        unsigned int removed = 0;
#pragma unroll
        for (int b = 0; b < 32; b++) {
            int j = lane * 32 + b;
            bool valid = (j < TOPK) && (out[j] >= CONF);
            if (!valid) removed |= (1u << b);
        }
        for (int cch = 0; cch < 32; cch++) {
            unsigned int buf[32];
#pragma unroll
            for (int b = 0; b < 32; b++)
                buf[b] = g_mask[(cch * 32 + b) * 32 + lane];
            unsigned int kept = 0;
            if (lane == cch) {
                unsigned int rm = removed;
#pragma unroll
                for (int b = 0; b < 32; b++) {
                    if (!((rm >> b) & 1u)) { kept |= 1u << b; rm |= buf[b]; }
                }
            }
            kept = __shfl_sync(0xffffffffu, kept, cch);
#pragma unroll
            for (int b = 0; b < 32; b++)
                if ((kept >> b) & 1u) removed |= buf[b];
        }
#pragma unroll
        for (int b = 0; b < 32; b++) {
            int j = lane * 32 + b;
            if (j < TOPK)
                out[6000 + j] = ((removed >> b) & 1u) ? 0.0f : 1.0f;  // keep
        }
    }
}

// ---------------- entry ----------------
extern "C" void kernel_launch(void* const* d_in, const int* in_sizes, int n_in,
                              void* d_out, int out_size) {
    const float* obj = (const float*)d_in[0];   // (1,9,256,256)
    const float* cls = (const float*)d_in[1];   // (1,720,256,256)
    const float* reg = (const float*)d_in[2];   // (1,36,256,256)
    const float* anc = (const float*)d_in[3];   // (589824,4)
    float* out = (float*)d_out;                 // [scores|labels|boxes|keep] = 7000

    k_zero<<<64, 1024>>>();
    k_score<<<NTOT / 128, 256>>>(obj, (const float4*)cls);
    k_scan<<<1, 1024>>>();
    k_collect<<<(NTOT / 4) / 256, 256>>>();
    k_tail<<<1, 1024>>>(obj, cls, reg, anc, out);
    (void)in_sizes; (void)n_in; (void)out_size;
}

// round 15
// speedup vs baseline: 2.6692x; 2.6692x over previous
#include <cuda_runtime.h>
#include <math.h>
#include <stdint.h>

#define HW      65536
#define HW4     16384
#define NA      9
#define NC      80
#define NTOT    (HW * NA)          // 589824
#define TOPK    1000
#define CONF    0.05f
#define NMST    0.6f
#define CTRC    32.0f
#define EXPC    18.420680743952367f   // log(1e8) -> f32
#define SCLC    4.1351665567423560f   // log(1000/16) -> f32
#define IMGF    2048.0f
#define CAP     4096

// ---------------- device scratch (no allocations allowed) ----------------
__device__ float              g_z[NTOT];          // fast logit (binning only)
__device__ float              g_m[NTOT];          // exact class max per anchor
__device__ unsigned int       g_hist[65536];
__device__ unsigned int       g_cnt;
__device__ int                g_bin;
__device__ unsigned int       g_candidx[CAP];     // stage-1: flat anchor idx
__device__ unsigned long long g_cand[CAP];        // stage-2: sort keys
__device__ int                g_topidx[TOPK];
__device__ int                g_toplab[TOPK];
__device__ float4             g_topbox[TOPK];
__device__ unsigned int       g_mask[1024 * 32];

// monotone float -> uint mapping (total order incl. negatives)
__device__ __forceinline__ unsigned int fmap(float f) {
    unsigned int b = __float_as_uint(f);
    return b ^ ((b & 0x80000000u) ? 0xFFFFFFFFu : 0x80000000u);
}

// =================== glibc (ARM optimized-routines) expf ===================
__constant__ unsigned long long EXP2F_TAB[32] = {
0x3ff0000000000000ULL, 0x3fefd9b0d3158574ULL, 0x3fefb5586cf9890fULL, 0x3fef9301d0125b51ULL,
0x3fef72b83c7d517bULL, 0x3fef54873168b9aaULL, 0x3fef387a6e756238ULL, 0x3fef1e9df51fdee1ULL,
0x3fef06fe0a31b715ULL, 0x3feef1a7373aa9cbULL, 0x3feedea64c123422ULL, 0x3feece086061892dULL,
0x3feebfdad5362a27ULL, 0x3feeb42b569d4f82ULL, 0x3feeab07dd485429ULL, 0x3feea47eb03a5585ULL,
0x3feea09e667f3bcdULL, 0x3fee9f75e8ec5f74ULL, 0x3feea11473eb0187ULL, 0x3feea589994cce13ULL,
0x3feeace5422aa0dbULL, 0x3feeb737b0cdc5e5ULL, 0x3feec49182a3f090ULL, 0x3feed503b23e255dULL,
0x3feee89f995ad3adULL, 0x3feeff76f2fb5e47ULL, 0x3fef199bdd85529cULL, 0x3fef3720dcef9069ULL,
0x3fef5818dcfba487ULL, 0x3fef7c97337b9b5fULL, 0x3fefa4afa2a490daULL, 0x3fefd0765b6e4540ULL };

__device__ __forceinline__ float glibc_expf(float x) {
    const double InvLn2N = 0x1.71547652b82fep+0 * 32.0;
    const double C0 = 0x1.c6af84b912394p-5 / 32.0 / 32.0 / 32.0;
    const double C1 = 0x1.ebfce50fac4f3p-3 / 32.0 / 32.0;
    const double C2 = 0x1.62e42ff0c52d6p-1 / 32.0;
    double xd = (double)x;
    double z  = InvLn2N * xd;
    double kd = nearbyint(z);
    long long ki = (long long)kd;
    double r  = z - kd;
    unsigned long long t = EXP2F_TAB[(int)(ki & 31)] + ((unsigned long long)ki << 47);
    double s  = __longlong_as_double((long long)t);
    double z2 = fma(C0, r, C1);
    double r2 = r * r;
    double y  = fma(C2, r, 1.0);
    y = fma(z2, r2, y);
    y = y * s;
    return (float)y;
}

// =================== glibc (ARM optimized-routines) logf ===================
__constant__ double LOGF_TAB[16][2] = {
 { 0x1.661ec79f8f3bep+0, -0x1.57bf7808caadep-2 },
 { 0x1.571ed4aaf883dp+0, -0x1.2bef0a7c06ddbp-2 },
 { 0x1.49539f0f010bp+0,  -0x1.01eae7f513a67p-2 },
 { 0x1.3c995b0b80385p+0, -0x1.b31d8a68224e9p-3 },
 { 0x1.30d190c8864a5p+0, -0x1.6574f0ac07758p-3 },
 { 0x1.25e227b0b8eap+0,  -0x1.1aa2bc79c81p-3  },
 { 0x1.1bb4a4a1a343fp+0, -0x1.a4e76ce8c0e5ep-4 },
 { 0x1.12358f08ae5bap+0, -0x1.1973c5a611cccp-4 },
 { 0x1.0953f419900a7p+0, -0x1.252f438e10c1ep-5 },
 { 0x1p+0,                0x0p+0              },
 { 0x1.e608cfd9a47acp-1,  0x1.aa5aa5df25984p-5 },
 { 0x1.ca4b31f026aap-1,   0x1.c5e53aa362eb4p-4 },
 { 0x1.b2036576afce6p-1,  0x1.526e57720db08p-3 },
 { 0x1.9c2d163a1aa2dp-1,  0x1.bc2860d224770p-3 },
 { 0x1.886e6037841edp-1,  0x1.1058bc8a07ee1p-2 },
 { 0x1.767dcf5534862p-1,  0x1.4043057b6ee09p-2 } };

__device__ __forceinline__ float glibc_logf(float x) {
    const double Ln2 = 0x1.62e42fefa39efp-1;
    const double A0 = -0x1.00ea348b88334p-2;
    const double A1 =  0x1.5575b0be00b6ap-2;
    const double A2 = -0x1.ffffef20a4123p-2;
    unsigned int ix = __float_as_uint(x);
    if (ix == 0x3f800000u) return 0.0f;
    unsigned int tmp = ix - 0x3f330000u;
    int i = (int)((tmp >> 19) & 15u);
    int k = (int)tmp >> 23;
    unsigned int iz = ix - (tmp & 0xff800000u);
    double invc = LOGF_TAB[i][0];
    double logc = LOGF_TAB[i][1];
    double z  = (double)__uint_as_float(iz);
    double r  = fma(z, invc, -1.0);
    double y0 = fma((double)k, Ln2, logc);
    double r2 = r * r;
    double y  = fma(A1, r, A2);
    y = fma(A0, r2, y);
    y = fma(y, r2, y0 + r);
    return (float)y;
}

// exact reference z: (m+o) - log(((1 + e^min(m,C)) + e^min(o,C)))
__device__ __forceinline__ float exact_z(float m, float o) {
    float e1 = glibc_expf(fminf(m, EXPC));
    float e2 = glibc_expf(fminf(o, EXPC));
    float L  = glibc_logf(__fadd_rn(__fadd_rn(1.0f, e1), e2));
    return __fsub_rn(__fadd_rn(m, o), L);
}
// exact reference sigmoid: 1 / (1 + exp(-z))
__device__ __forceinline__ float exact_sig(float z) {
    float e = glibc_expf(__fsub_rn(0.0f, z));
    return __fdiv_rn(1.0f, __fadd_rn(1.0f, e));
}

// fast libdevice z (binning only; within a few ulps of exact)
__device__ __forceinline__ float fast_z(float m, float o) {
    return (m + o) - logf((1.0f + expf(fminf(m, EXPC))) + expf(fminf(o, EXPC)));
}

__device__ __forceinline__ float4 max4(float4 a, float4 b) {
    return make_float4(fmaxf(a.x, b.x), fmaxf(a.y, b.y),
                       fmaxf(a.z, b.z), fmaxf(a.w, b.w));
}

// ---------------- K0: zero histogram + counter ----------------
__global__ void k_zero() {
    int t = blockIdx.x * blockDim.x + threadIdx.x;
    if (t < 65536) g_hist[t] = 0u;
    if (t == 0) g_cnt = 0u;
}

// ---------------- K1: 512-px tile, 2KB-contiguous class-row reads -------
// Block (256 thr, 8 warps) handles a 512-pixel tile of one anchor.
// Warp w covers class rows w, w+8, ..., w+72 over 4 positions; each
// (row, position) read is 512B/warp, 4 positions -> 2KB contiguous per row.
__global__ __launch_bounds__(256, 4) void k_score(const float* __restrict__ obj,
                                                  const float4* __restrict__ cls4) {
    __shared__ float part[8][512];           // 16KB
    int lane = threadIdx.x & 31;
    int w    = threadIdx.x >> 5;
    int a    = blockIdx.x >> 7;              // 128 tiles per anchor
    int tile = blockIdx.x & 127;
    int G0   = tile << 7;                    // first float4-group of tile (128)

    const float4* base = cls4 + (((size_t)(a * NC + w)) << 14) + G0 + lane;
#pragma unroll
    for (int pos = 0; pos < 4; pos++) {
        float4 v[10];
#pragma unroll
        for (int cc = 0; cc < 10; cc++)      // 10 indep LDG.128, reg-batched
            v[cc] = base[pos * 32 + ((size_t)(cc * 8) << 14)];
        float4 m01 = max4(v[0], v[1]);
        float4 m23 = max4(v[2], v[3]);
        float4 m45 = max4(v[4], v[5]);
        float4 m67 = max4(v[6], v[7]);
        float4 m89 = max4(v[8], v[9]);
        float4 m4 = max4(max4(max4(m01, m23), max4(m45, m67)), m89);
        ((float4*)part[w])[pos * 32 + lane] = m4;
    }
    __syncthreads();
    // finalize: 256 threads, 2 pixels each
#pragma unroll
    for (int h = 0; h < 2; h++) {
        int p = threadIdx.x + h * 256;       // pixel within tile [0,512)
        float m = part[0][p];
#pragma unroll
        for (int r = 1; r < 8; r++) m = fmaxf(m, part[r][p]);
        int gidx = (a << 16) + (tile << 9) + p;   // global anchor index
        float o = obj[gidx];
        float z = fast_z(m, o);
        g_z[gidx] = z;
        g_m[gidx] = m;
        atomicAdd(&g_hist[fmap(z) >> 16], 1u);
    }
}

// ---------------- K2: threshold bin via parallel block scan -------------
__global__ void k_scan() {
    __shared__ unsigned int sS[1024];
    __shared__ unsigned int sP[1024];
    __shared__ unsigned int sWarp[32];
    __shared__ unsigned int sH[64];
    int tid = threadIdx.x;
    int lane = tid & 31, wid = tid >> 5;

    unsigned int s = 0;
#pragma unroll 8
    for (int b = 0; b < 64; b++) s += g_hist[tid * 64 + b];
    sS[tid] = s;

    unsigned int p = s;
#pragma unroll
    for (int d = 1; d < 32; d <<= 1) {
        unsigned int v = __shfl_up_sync(0xffffffffu, p, d);
        if (lane >= d) p += v;
    }
    if (lane == 31) sWarp[wid] = p;
    __syncthreads();
    if (tid < 32) {
        unsigned int w = sWarp[tid];
#pragma unroll
        for (int d = 1; d < 32; d <<= 1) {
            unsigned int v = __shfl_up_sync(0xffffffffu, w, d);
            if (tid >= d) w += v;
        }
        sWarp[tid] = w;
    }
    __syncthreads();
    unsigned int P = p + (wid ? sWarp[wid - 1] : 0u);
    sP[tid] = P;
    __syncthreads();
    unsigned int T = sP[1023];
    unsigned int suff = T - P + s;
    int n = __syncthreads_count(suff >= TOPK);
    int C = n - 1;
    if (tid < 64) sH[tid] = g_hist[C * 64 + tid];
    __syncthreads();
    if (tid == 0) {
        unsigned int acc = T - sP[C];
        int bin = C * 64;
        for (int b = 63; b >= 0; b--) {
            acc += sH[b];
            if (acc >= TOPK) { bin = C * 64 + b; break; }
        }
        g_bin = bin;
    }
}

// ---------------- K3: collect candidate indices (no math) ---------------
__global__ void k_collect() {
    int t4 = blockIdx.x * blockDim.x + threadIdx.x;   // [0, NTOT/4)
    float4 z4 = ((const float4*)g_z)[t4];
    int binm1 = g_bin - 1;
    bool c0 = (int)(fmap(z4.x) >> 16) >= binm1;
    bool c1 = (int)(fmap(z4.y) >> 16) >= binm1;
    bool c2 = (int)(fmap(z4.z) >> 16) >= binm1;
    bool c3 = (int)(fmap(z4.w) >> 16) >= binm1;
    if (!(c0 | c1 | c2 | c3)) return;
#pragma unroll
    for (int k = 0; k < 4; k++) {
        bool c = (k == 0) ? c0 : (k == 1) ? c1 : (k == 2) ? c2 : c3;
        if (!c) continue;
        unsigned int p = atomicAdd(&g_cnt, 1u);
        if (p < CAP) g_candidx[p] = (unsigned int)(t4 * 4 + k);
    }
}

// ---------------- K3b: exact glibc math on balanced candidates ----------
__global__ void k_exact(const float* __restrict__ obj) {
    int i = blockIdx.x * blockDim.x + threadIdx.x;    // [0, CAP)
    unsigned int cnt = g_cnt;
    if (cnt > CAP) cnt = CAP;
    if (i >= (int)cnt) return;
    int t = (int)g_candidx[i];
    float m = g_m[t];
    float o = obj[t];
    float s = exact_sig(exact_z(m, o));   // bit-matched to reference
    unsigned int sb = __float_as_uint(s);
    int a = t >> 16;
    int pix = t & (HW - 1);
    unsigned int n = (unsigned int)(pix * NA + a);
    // higher s first; equal s -> lower index first (JAX top_k)
    g_cand[i] = ((unsigned long long)sb << 32) | (unsigned long long)(~n);
}

// ---------------- K4: dynamic-size bitonic sort, emit top-1000 ----------
__global__ void k_sort(float* __restrict__ out) {
    __shared__ unsigned long long sk[CAP];
    int tid = threadIdx.x;
    unsigned int c = g_cnt;
    if (c > CAP) c = CAP;
    int S = 1024;
    while (S < (int)c) S <<= 1;               // smallest pow2 >= cnt (>=1024)
    for (int i = tid; i < S; i += 1024)
        sk[i] = (i < (int)c) ? g_cand[i] : 0ULL;
    __syncthreads();
    for (int k = 2; k <= S; k <<= 1) {
        for (int j = k >> 1; j > 0; j >>= 1) {
            for (int i = tid; i < S; i += 1024) {
                int ixj = i ^ j;
                if (ixj > i) {
                    unsigned long long A = sk[i], B = sk[ixj];
                    bool dsc = ((i & k) == 0);
                    if (dsc ? (A < B) : (A > B)) { sk[i] = B; sk[ixj] = A; }
                }
            }
            __syncthreads();
        }
    }
    if (tid < TOPK) {
        unsigned long long key = sk[tid];
        out[tid] = __uint_as_float((unsigned int)(key >> 32));   // scores
        g_topidx[tid] = (int)(~(unsigned int)key);
    }
}

// ---------------- K5: decode, one warp per finalist ---------------------
__global__ void k_decode(const float* __restrict__ cls,
                         const float* __restrict__ reg,
                         const float* __restrict__ anc,
                         float* __restrict__ out) {
    int gw = (blockIdx.x * blockDim.x + threadIdx.x) >> 5;
    int lane = threadIdx.x & 31;
    if (gw >= TOPK) return;
    int n = g_topidx[gw];
    int pix = n / NA;
    int a = n - pix * NA;
    const float* cp = cls + ((size_t)(a * NC) << 16) + pix;
    float m = -3.4e38f;
    int lbl = NC;
    for (int c = lane; c < NC; c += 32) {
        float v = cp[(size_t)c << 16];
        if (v > m) { m = v; lbl = c; }        // per-lane first occurrence
    }
#pragma unroll
    for (int d = 16; d; d >>= 1) {
        float vm = __shfl_down_sync(0xffffffffu, m, d);
        int vl = __shfl_down_sync(0xffffffffu, lbl, d);
        if (vm > m || (vm == m && vl < lbl)) { m = vm; lbl = vl; }
    }
    if (lane == 0) {
        const float* rp = reg + ((size_t)(a * 4) << 16) + pix;
        float r0 = rp[0];
        float r1 = rp[(size_t)1 << 16];
        float r2 = rp[(size_t)2 << 16];
        float r3 = rp[(size_t)3 << 16];
        float ax = anc[n * 4 + 0], ay = anc[n * 4 + 1];
        float aw = anc[n * 4 + 2], ah = anc[n * 4 + 3];
        float ox = fminf(fmaxf(__fmul_rn(r0, aw), -CTRC), CTRC);
        float oy = fminf(fmaxf(__fmul_rn(r1, ah), -CTRC), CTRC);
        float cx = __fadd_rn(ax, ox);
        float cy = __fadd_rn(ay, oy);
        float w = __fmul_rn(aw, glibc_expf(fminf(r2, SCLC)));
        float h = __fmul_rn(ah, glibc_expf(fminf(r3, SCLC)));
        float hw = __fmul_rn(0.5f, w);
        float hh = __fmul_rn(0.5f, h);
        float x1 = fminf(fmaxf(__fdiv_rn(__fsub_rn(cx, hw), IMGF), 0.0f), 1.0f);
        float y1 = fminf(fmaxf(__fdiv_rn(__fsub_rn(cy, hh), IMGF), 0.0f), 1.0f);
        float x2 = fminf(fmaxf(__fdiv_rn(__fadd_rn(cx, hw), IMGF), 0.0f), 1.0f);
        float y2 = fminf(fmaxf(__fdiv_rn(__fadd_rn(cy, hh), IMGF), 0.0f), 1.0f);
        out[1000 + gw] = (float)lbl;                 // labels
        out[2000 + gw * 4 + 0] = x1;                 // boxes
        out[2000 + gw * 4 + 1] = y1;
        out[2000 + gw * 4 + 2] = x2;
        out[2000 + gw * 4 + 3] = y2;
        g_toplab[gw] = lbl;
        g_topbox[gw] = make_float4(x1, y1, x2, y2);
    }
}

// ---------------- K6: suppression bitmask (1000 x 1000) -----------------
__global__ void k_mask() {
    int i = blockIdx.x;
    float4 bi = g_topbox[i];
    int li = g_toplab[i];
    float areai = __fmul_rn(__fsub_rn(bi.z, bi.x), __fsub_rn(bi.w, bi.y));
    int warp = threadIdx.x >> 5;
    int lane = threadIdx.x & 31;
    int j = warp * 32 + lane;
    bool sup = false;
    if (j < TOPK && j > i) {
        if (g_toplab[j] == li) {
            float4 bj = g_topbox[j];
            float xx1 = fmaxf(bi.x, bj.x);
            float yy1 = fmaxf(bi.y, bj.y);
            float xx2 = fminf(bi.z, bj.z);
            float yy2 = fminf(bi.w, bj.w);
            float inter = __fmul_rn(fmaxf(1e-28f, __fsub_rn(xx2, xx1)),
                                    fmaxf(1e-28f, __fsub_rn(yy2, yy1)));
            float areaj = __fmul_rn(__fsub_rn(bj.z, bj.x), __fsub_rn(bj.w, bj.y));
            float denom = __fadd_rn(__fsub_rn(__fadd_rn(areai, areaj), inter), 1e-14f);
            float iou = __fdiv_rn(inter, denom);
            sup = iou > NMST;
        }
    }
    unsigned int b = __ballot_sync(0xffffffffu, sup);
    if (lane == 0) g_mask[i * 32 + warp] = b;
}

// ---------------- K7: chunked greedy scan (1 warp) ----------------------
__device__ __forceinline__ void nms_load(unsigned int (&buf)[32], int cch, int lane) {
#pragma unroll
    for (int b = 0; b < 32; b++)
        buf[b] = g_mask[(cch * 32 + b) * 32 + lane];
}
__device__ __forceinline__ void nms_proc(unsigned int (&buf)[32], int cch,
                                         int lane, unsigned int& removed) {
    unsigned int kept = 0;
    if (lane == cch) {
        unsigned int rm = removed;
#pragma unroll
        for (int b = 0; b < 32; b++) {
            if (!((rm >> b) & 1u)) { kept |= 1u << b; rm |= buf[b]; }
        }
    }
    kept = __shfl_sync(0xffffffffu, kept, cch);
#pragma unroll
    for (int b = 0; b < 32; b++)
        if ((kept >> b) & 1u) removed |= buf[b];
}
__global__ void k_nms(float* __restrict__ out) {
    int lane = threadIdx.x;   // 32 threads; lane l owns keep-word l
    unsigned int removed = 0;
#pragma unroll
    for (int b = 0; b < 32; b++) {
        int j = lane * 32 + b;
        bool valid = (j < TOPK) && (out[j] >= CONF);
        if (!valid) removed |= (1u << b);
    }
    unsigned int bufA[32], bufB[32];
    nms_load(bufA, 0, lane);
    for (int cc = 0; cc < 32; cc += 2) {
        if (cc + 1 < 32) nms_load(bufB, cc + 1, lane);
        nms_proc(bufA, cc, lane, removed);
        if (cc + 2 < 32) nms_load(bufA, cc + 2, lane);
        if (cc + 1 < 32) nms_proc(bufB, cc + 1, lane, removed);
    }
#pragma unroll
    for (int b = 0; b < 32; b++) {
        int j = lane * 32 + b;
        if (j < TOPK)
            out[6000 + j] = ((removed >> b) & 1u) ? 0.0f : 1.0f;  // keep
    }
}

// ---------------- entry ----------------
extern "C" void kernel_launch(void* const* d_in, const int* in_sizes, int n_in,
                              void* d_out, int out_size) {
    const float* obj = (const float*)d_in[0];   // (1,9,256,256)
    const float* cls = (const float*)d_in[1];   // (1,720,256,256)
    const float* reg = (const float*)d_in[2];   // (1,36,256,256)
    const float* anc = (const float*)d_in[3];   // (589824,4)
    float* out = (float*)d_out;                 // [scores|labels|boxes|keep] = 7000

    k_zero<<<64, 1024>>>();
    k_score<<<1152, 256>>>(obj, (const float4*)cls);
    k_scan<<<1, 1024>>>();
    k_collect<<<(NTOT / 4) / 256, 256>>>();
    k_exact<<<CAP / 256, 256>>>(obj);
    k_sort<<<1, 1024>>>(out);
    k_decode<<<(TOPK * 32) / 256, 256>>>(cls, reg, anc, out);
    k_mask<<<TOPK, 1024>>>();
    k_nms<<<1, 32>>>(out);
    (void)in_sizes; (void)n_in; (void)out_size;
}

// round 16
// speedup vs baseline: 2.8818x; 1.0796x over previous
#include <cuda_runtime.h>
#include <math.h>
#include <stdint.h>

#define HW      65536
#define HW4     16384
#define NA      9
#define NC      80
#define NTOT    (HW * NA)          // 589824
#define TOPK    1000
#define CONF    0.05f
#define NMST    0.6f
#define CTRC    32.0f
#define EXPC    18.420680743952367f   // log(1e8) -> f32
#define SCLC    4.1351665567423560f   // log(1000/16) -> f32
#define IMGF    2048.0f
#define CAP     4096

// ---------------- device scratch (no allocations allowed) ----------------
// g_hist / g_cnt are zero-initialized at load; k_scan re-zeroes them each
// run so no separate zeroing launch is needed.
__device__ float              g_z[NTOT];          // fast logit (binning only)
__device__ float              g_m[NTOT];          // exact class max per anchor
__device__ unsigned int       g_hist[65536];
__device__ unsigned int       g_cnt;
__device__ int                g_bin;
__device__ unsigned int       g_candidx[CAP];     // stage-1: flat anchor idx
__device__ unsigned long long g_cand[CAP];        // stage-2: sort keys
__device__ int                g_topidx[TOPK];
__device__ int                g_toplab[TOPK];
__device__ float4             g_topbox[TOPK];
__device__ unsigned int       g_mask[1024 * 32];

// monotone float -> uint mapping (total order incl. negatives)
__device__ __forceinline__ unsigned int fmap(float f) {
    unsigned int b = __float_as_uint(f);
    return b ^ ((b & 0x80000000u) ? 0xFFFFFFFFu : 0x80000000u);
}

// =================== glibc (ARM optimized-routines) expf ===================
__constant__ unsigned long long EXP2F_TAB[32] = {
0x3ff0000000000000ULL, 0x3fefd9b0d3158574ULL, 0x3fefb5586cf9890fULL, 0x3fef9301d0125b51ULL,
0x3fef72b83c7d517bULL, 0x3fef54873168b9aaULL, 0x3fef387a6e756238ULL, 0x3fef1e9df51fdee1ULL,
0x3fef06fe0a31b715ULL, 0x3feef1a7373aa9cbULL, 0x3feedea64c123422ULL, 0x3feece086061892dULL,
0x3feebfdad5362a27ULL, 0x3feeb42b569d4f82ULL, 0x3feeab07dd485429ULL, 0x3feea47eb03a5585ULL,
0x3feea09e667f3bcdULL, 0x3fee9f75e8ec5f74ULL, 0x3feea11473eb0187ULL, 0x3feea589994cce13ULL,
0x3feeace5422aa0dbULL, 0x3feeb737b0cdc5e5ULL, 0x3feec49182a3f090ULL, 0x3feed503b23e255dULL,
0x3feee89f995ad3adULL, 0x3feeff76f2fb5e47ULL, 0x3fef199bdd85529cULL, 0x3fef3720dcef9069ULL,
0x3fef5818dcfba487ULL, 0x3fef7c97337b9b5fULL, 0x3fefa4afa2a490daULL, 0x3fefd0765b6e4540ULL };

__device__ __forceinline__ float glibc_expf(float x) {
    const double InvLn2N = 0x1.71547652b82fep+0 * 32.0;
    const double C0 = 0x1.c6af84b912394p-5 / 32.0 / 32.0 / 32.0;
    const double C1 = 0x1.ebfce50fac4f3p-3 / 32.0 / 32.0;
    const double C2 = 0x1.62e42ff0c52d6p-1 / 32.0;
    double xd = (double)x;
    double z  = InvLn2N * xd;
    double kd = nearbyint(z);
    long long ki = (long long)kd;
    double r  = z - kd;
    unsigned long long t = EXP2F_TAB[(int)(ki & 31)] + ((unsigned long long)ki << 47);
    double s  = __longlong_as_double((long long)t);
    double z2 = fma(C0, r, C1);
    double r2 = r * r;
    double y  = fma(C2, r, 1.0);
    y = fma(z2, r2, y);
    y = y * s;
    return (float)y;
}

// =================== glibc (ARM optimized-routines) logf ===================
__constant__ double LOGF_TAB[16][2] = {
 { 0x1.661ec79f8f3bep+0, -0x1.57bf7808caadep-2 },
 { 0x1.571ed4aaf883dp+0, -0x1.2bef0a7c06ddbp-2 },
 { 0x1.49539f0f010bp+0,  -0x1.01eae7f513a67p-2 },
 { 0x1.3c995b0b80385p+0, -0x1.b31d8a68224e9p-3 },
 { 0x1.30d190c8864a5p+0, -0x1.6574f0ac07758p-3 },
 { 0x1.25e227b0b8eap+0,  -0x1.1aa2bc79c81p-3  },
 { 0x1.1bb4a4a1a343fp+0, -0x1.a4e76ce8c0e5ep-4 },
 { 0x1.12358f08ae5bap+0, -0x1.1973c5a611cccp-4 },
 { 0x1.0953f419900a7p+0, -0x1.252f438e10c1ep-5 },
 { 0x1p+0,                0x0p+0              },
 { 0x1.e608cfd9a47acp-1,  0x1.aa5aa5df25984p-5 },
 { 0x1.ca4b31f026aap-1,   0x1.c5e53aa362eb4p-4 },
 { 0x1.b2036576afce6p-1,  0x1.526e57720db08p-3 },
 { 0x1.9c2d163a1aa2dp-1,  0x1.bc2860d224770p-3 },
 { 0x1.886e6037841edp-1,  0x1.1058bc8a07ee1p-2 },
 { 0x1.767dcf5534862p-1,  0x1.4043057b6ee09p-2 } };

__device__ __forceinline__ float glibc_logf(float x) {
    const double Ln2 = 0x1.62e42fefa39efp-1;
    const double A0 = -0x1.00ea348b88334p-2;
    const double A1 =  0x1.5575b0be00b6ap-2;
    const double A2 = -0x1.ffffef20a4123p-2;
    unsigned int ix = __float_as_uint(x);
    if (ix == 0x3f800000u) return 0.0f;
    unsigned int tmp = ix - 0x3f330000u;
    int i = (int)((tmp >> 19) & 15u);
    int k = (int)tmp >> 23;
    unsigned int iz = ix - (tmp & 0xff800000u);
    double invc = LOGF_TAB[i][0];
    double logc = LOGF_TAB[i][1];
    double z  = (double)__uint_as_float(iz);
    double r  = fma(z, invc, -1.0);
    double y0 = fma((double)k, Ln2, logc);
    double r2 = r * r;
    double y  = fma(A1, r, A2);
    y = fma(A0, r2, y);
    y = fma(y, r2, y0 + r);
    return (float)y;
}

// exact reference z: (m+o) - log(((1 + e^min(m,C)) + e^min(o,C)))
__device__ __forceinline__ float exact_z(float m, float o) {
    float e1 = glibc_expf(fminf(m, EXPC));
    float e2 = glibc_expf(fminf(o, EXPC));
    float L  = glibc_logf(__fadd_rn(__fadd_rn(1.0f, e1), e2));
    return __fsub_rn(__fadd_rn(m, o), L);
}
// exact reference sigmoid: 1 / (1 + exp(-z))
__device__ __forceinline__ float exact_sig(float z) {
    float e = glibc_expf(__fsub_rn(0.0f, z));
    return __fdiv_rn(1.0f, __fadd_rn(1.0f, e));
}

// fast libdevice z (binning only; within a few ulps of exact)
__device__ __forceinline__ float fast_z(float m, float o) {
    return (m + o) - logf((1.0f + expf(fminf(m, EXPC))) + expf(fminf(o, EXPC)));
}

__device__ __forceinline__ float4 max4(float4 a, float4 b) {
    return make_float4(fmaxf(a.x, b.x), fmaxf(a.y, b.y),
                       fmaxf(a.z, b.z), fmaxf(a.w, b.w));
}

// ---------------- K1: warp-per-class-row, 256-px tile (R11 best) --------
// Block (256 thr, 8 warps) handles a 256-pixel tile of one anchor.
// Warp w loads classes w, w+8, ..., 2 adjacent groups per lane -> row-paired
// 512B issues (1KB contiguous per class row).
__global__ __launch_bounds__(256) void k_score(const float* __restrict__ obj,
                                               const float4* __restrict__ cls4) {
    __shared__ float4 part4[8][64];
    int lane = threadIdx.x & 31;
    int w    = threadIdx.x >> 5;
    int G0   = blockIdx.x << 6;              // first float4-group of tile (64/tile)
    int a    = G0 >> 14;                     // anchor (uniform in block)
    int q    = G0 & (HW4 - 1);

    const float4* base = cls4 + (((size_t)(a * NC + w)) << 14) + q;
    float4 ma = base[lane];
    float4 mb = base[lane + 32];
#pragma unroll
    for (int cc = 1; cc < 10; cc++) {        // classes w+8*cc
        size_t off = (size_t)(cc * 8) << 14;
        float4 va = base[off + lane];
        float4 vb = base[off + lane + 32];
        ma = max4(ma, va);
        mb = max4(mb, vb);
    }
    part4[w][lane] = ma;
    part4[w][lane + 32] = mb;
    __syncthreads();
    // finalize: 256 threads, one pixel each
    int p = threadIdx.x;
    const float* partf = (const float*)part4;     // [8][256]
    float m = partf[p];
#pragma unroll
    for (int r = 1; r < 8; r++) m = fmaxf(m, partf[r * 256 + p]);
    int gidx = (G0 << 2) + p;                // global anchor index
    float o = obj[gidx];
    float z = fast_z(m, o);
    g_z[gidx] = z;
    g_m[gidx] = m;
    atomicAdd(&g_hist[fmap(z) >> 16], 1u);
}

// ---------------- K2: threshold bin via parallel block scan -------------
// Also re-zeroes g_hist and g_cnt for the next graph replay (fire-and-forget
// stores after the final histogram read).
__global__ void k_scan() {
    __shared__ unsigned int sS[1024];
    __shared__ unsigned int sP[1024];
    __shared__ unsigned int sWarp[32];
    __shared__ unsigned int sH[64];
    int tid = threadIdx.x;
    int lane = tid & 31, wid = tid >> 5;

    unsigned int s = 0;
#pragma unroll 8
    for (int b = 0; b < 64; b++) s += g_hist[tid * 64 + b];
    sS[tid] = s;

    unsigned int p = s;
#pragma unroll
    for (int d = 1; d < 32; d <<= 1) {
        unsigned int v = __shfl_up_sync(0xffffffffu, p, d);
        if (lane >= d) p += v;
    }
    if (lane == 31) sWarp[wid] = p;
    __syncthreads();
    if (tid < 32) {
        unsigned int w = sWarp[tid];
#pragma unroll
        for (int d = 1; d < 32; d <<= 1) {
            unsigned int v = __shfl_up_sync(0xffffffffu, w, d);
            if (tid >= d) w += v;
        }
        sWarp[tid] = w;
    }
    __syncthreads();
    unsigned int P = p + (wid ? sWarp[wid - 1] : 0u);
    sP[tid] = P;
    __syncthreads();
    unsigned int T = sP[1023];
    unsigned int suff = T - P + s;
    int n = __syncthreads_count(suff >= TOPK);
    int C = n - 1;
    if (tid < 64) sH[tid] = g_hist[C * 64 + tid];
    __syncthreads();
    // hist fully consumed -> zero it for the next replay (coalesced uint4)
    {
        uint4 zz = make_uint4(0u, 0u, 0u, 0u);
        uint4* h4 = (uint4*)g_hist;
#pragma unroll
        for (int b = 0; b < 16; b++) h4[b * 1024 + tid] = zz;
    }
    if (tid == 0) {
        g_cnt = 0u;
        unsigned int acc = T - sP[C];
        int bin = C * 64;
        for (int b = 63; b >= 0; b--) {
            acc += sH[b];
            if (acc >= TOPK) { bin = C * 64 + b; break; }
        }
        g_bin = bin;
    }
}

// ---------------- K3: collect candidate indices (no math) ---------------
__global__ void k_collect() {
    int t4 = blockIdx.x * blockDim.x + threadIdx.x;   // [0, NTOT/4)
    float4 z4 = ((const float4*)g_z)[t4];
    int binm1 = g_bin - 1;
    bool c0 = (int)(fmap(z4.x) >> 16) >= binm1;
    bool c1 = (int)(fmap(z4.y) >> 16) >= binm1;
    bool c2 = (int)(fmap(z4.z) >> 16) >= binm1;
    bool c3 = (int)(fmap(z4.w) >> 16) >= binm1;
    if (!(c0 | c1 | c2 | c3)) return;
#pragma unroll
    for (int k = 0; k < 4; k++) {
        bool c = (k == 0) ? c0 : (k == 1) ? c1 : (k == 2) ? c2 : c3;
        if (!c) continue;
        unsigned int p = atomicAdd(&g_cnt, 1u);
        if (p < CAP) g_candidx[p] = (unsigned int)(t4 * 4 + k);
    }
}

// ---------------- K3b: exact glibc math on balanced candidates ----------
__global__ void k_exact(const float* __restrict__ obj) {
    int i = blockIdx.x * blockDim.x + threadIdx.x;    // [0, CAP)
    unsigned int cnt = g_cnt;
    if (cnt > CAP) cnt = CAP;
    if (i >= (int)cnt) return;
    int t = (int)g_candidx[i];
    float m = g_m[t];
    float o = obj[t];
    float s = exact_sig(exact_z(m, o));   // bit-matched to reference
    unsigned int sb = __float_as_uint(s);
    int a = t >> 16;
    int pix = t & (HW - 1);
    unsigned int n = (unsigned int)(pix * NA + a);
    // higher s first; equal s -> lower index first (JAX top_k)
    g_cand[i] = ((unsigned long long)sb << 32) | (unsigned long long)(~n);
}

// ---------------- K4: dynamic-size bitonic sort, emit top-1000 ----------
__global__ void k_sort(float* __restrict__ out) {
    __shared__ unsigned long long sk[CAP];
    int tid = threadIdx.x;
    unsigned int c = g_cnt;
    if (c > CAP) c = CAP;
    int S = 1024;
    while (S < (int)c) S <<= 1;               // smallest pow2 >= cnt (>=1024)
    for (int i = tid; i < S; i += 1024)
        sk[i] = (i < (int)c) ? g_cand[i] : 0ULL;
    __syncthreads();
    for (int k = 2; k <= S; k <<= 1) {
        for (int j = k >> 1; j > 0; j >>= 1) {
            for (int i = tid; i < S; i += 1024) {
                int ixj = i ^ j;
                if (ixj > i) {
                    unsigned long long A = sk[i], B = sk[ixj];
                    bool dsc = ((i & k) == 0);
                    if (dsc ? (A < B) : (A > B)) { sk[i] = B; sk[ixj] = A; }
                }
            }
            __syncthreads();
        }
    }
    if (tid < TOPK) {
        unsigned long long key = sk[tid];
        out[tid] = __uint_as_float((unsigned int)(key >> 32));   // scores
        g_topidx[tid] = (int)(~(unsigned int)key);
    }
}

// ---------------- K5: decode, one warp per finalist ---------------------
__global__ void k_decode(const float* __restrict__ cls,
                         const float* __restrict__ reg,
                         const float* __restrict__ anc,
                         float* __restrict__ out) {
    int gw = (blockIdx.x * blockDim.x + threadIdx.x) >> 5;
    int lane = threadIdx.x & 31;
    if (gw >= TOPK) return;
    int n = g_topidx[gw];
    int pix = n / NA;
    int a = n - pix * NA;
    const float* cp = cls + ((size_t)(a * NC) << 16) + pix;
    float m = -3.4e38f;
    int lbl = NC;
    for (int c = lane; c < NC; c += 32) {
        float v = cp[(size_t)c << 16];
        if (v > m) { m = v; lbl = c; }        // per-lane first occurrence
    }
#pragma unroll
    for (int d = 16; d; d >>= 1) {
        float vm = __shfl_down_sync(0xffffffffu, m, d);
        int vl = __shfl_down_sync(0xffffffffu, lbl, d);
        if (vm > m || (vm == m && vl < lbl)) { m = vm; lbl = vl; }
    }
    if (lane == 0) {
        const float* rp = reg + ((size_t)(a * 4) << 16) + pix;
        float r0 = rp[0];
        float r1 = rp[(size_t)1 << 16];
        float r2 = rp[(size_t)2 << 16];
        float r3 = rp[(size_t)3 << 16];
        float ax = anc[n * 4 + 0], ay = anc[n * 4 + 1];
        float aw = anc[n * 4 + 2], ah = anc[n * 4 + 3];
        float ox = fminf(fmaxf(__fmul_rn(r0, aw), -CTRC), CTRC);
        float oy = fminf(fmaxf(__fmul_rn(r1, ah), -CTRC), CTRC);
        float cx = __fadd_rn(ax, ox);
        float cy = __fadd_rn(ay, oy);
        float w = __fmul_rn(aw, glibc_expf(fminf(r2, SCLC)));
        float h = __fmul_rn(ah, glibc_expf(fminf(r3, SCLC)));
        float hw = __fmul_rn(0.5f, w);
        float hh = __fmul_rn(0.5f, h);
        float x1 = fminf(fmaxf(__fdiv_rn(__fsub_rn(cx, hw), IMGF), 0.0f), 1.0f);
        float y1 = fminf(fmaxf(__fdiv_rn(__fsub_rn(cy, hh), IMGF), 0.0f), 1.0f);
        float x2 = fminf(fmaxf(__fdiv_rn(__fadd_rn(cx, hw), IMGF), 0.0f), 1.0f);
        float y2 = fminf(fmaxf(__fdiv_rn(__fadd_rn(cy, hh), IMGF), 0.0f), 1.0f);
        out[1000 + gw] = (float)lbl;                 // labels
        out[2000 + gw * 4 + 0] = x1;                 // boxes
        out[2000 + gw * 4 + 1] = y1;
        out[2000 + gw * 4 + 2] = x2;
        out[2000 + gw * 4 + 3] = y2;
        g_toplab[gw] = lbl;
        g_topbox[gw] = make_float4(x1, y1, x2, y2);
    }
}

// ---------------- K6: suppression bitmask (1000 x 1000) -----------------
__global__ void k_mask() {
    int i = blockIdx.x;
    float4 bi = g_topbox[i];
    int li = g_toplab[i];
    float areai = __fmul_rn(__fsub_rn(bi.z, bi.x), __fsub_rn(bi.w, bi.y));
    int warp = threadIdx.x >> 5;
    int lane = threadIdx.x & 31;
    int j = warp * 32 + lane;
    bool sup = false;
    if (j < TOPK && j > i) {
        if (g_toplab[j] == li) {
            float4 bj = g_topbox[j];
            float xx1 = fmaxf(bi.x, bj.x);
            float yy1 = fmaxf(bi.y, bj.y);
            float xx2 = fminf(bi.z, bj.z);
            float yy2 = fminf(bi.w, bj.w);
            float inter = __fmul_rn(fmaxf(1e-28f, __fsub_rn(xx2, xx1)),
                                    fmaxf(1e-28f, __fsub_rn(yy2, yy1)));
            float areaj = __fmul_rn(__fsub_rn(bj.z, bj.x), __fsub_rn(bj.w, bj.y));
            float denom = __fadd_rn(__fsub_rn(__fadd_rn(areai, areaj), inter), 1e-14f);
            float iou = __fdiv_rn(inter, denom);
            sup = iou > NMST;
        }
    }
    unsigned int b = __ballot_sync(0xffffffffu, sup);
    if (lane == 0) g_mask[i * 32 + warp] = b;
}

// ---------------- K7: chunked greedy scan (1 warp) ----------------------
__device__ __forceinline__ void nms_load(unsigned int (&buf)[32], int cch, int lane) {
#pragma unroll
    for (int b = 0; b < 32; b++)
        buf[b] = g_mask[(cch * 32 + b) * 32 + lane];
}
__device__ __forceinline__ void nms_proc(unsigned int (&buf)[32], int cch,
                                         int lane, unsigned int& removed) {
    unsigned int kept = 0;
    if (lane == cch) {
        unsigned int rm = removed;
#pragma unroll
        for (int b = 0; b < 32; b++) {
            if (!((rm >> b) & 1u)) { kept |= 1u << b; rm |= buf[b]; }
        }
    }
    kept = __shfl_sync(0xffffffffu, kept, cch);
#pragma unroll
    for (int b = 0; b < 32; b++)
        if ((kept >> b) & 1u) removed |= buf[b];
}
__global__ void k_nms(float* __restrict__ out) {
    int lane = threadIdx.x;   // 32 threads; lane l owns keep-word l
    unsigned int removed = 0;
#pragma unroll
    for (int b = 0; b < 32; b++) {
        int j = lane * 32 + b;
        bool valid = (j < TOPK) && (out[j] >= CONF);
        if (!valid) removed |= (1u << b);
    }
    unsigned int bufA[32], bufB[32];
    nms_load(bufA, 0, lane);
    for (int cc = 0; cc < 32; cc += 2) {
        if (cc + 1 < 32) nms_load(bufB, cc + 1, lane);
        nms_proc(bufA, cc, lane, removed);
        if (cc + 2 < 32) nms_load(bufA, cc + 2, lane);
        if (cc + 1 < 32) nms_proc(bufB, cc + 1, lane, removed);
    }
#pragma unroll
    for (int b = 0; b < 32; b++) {
        int j = lane * 32 + b;
        if (j < TOPK)
            out[6000 + j] = ((removed >> b) & 1u) ? 0.0f : 1.0f;  // keep
    }
}

// ---------------- entry ----------------
extern "C" void kernel_launch(void* const* d_in, const int* in_sizes, int n_in,
                              void* d_out, int out_size) {
    const float* obj = (const float*)d_in[0];   // (1,9,256,256)
    const float* cls = (const float*)d_in[1];   // (1,720,256,256)
    const float* reg = (const float*)d_in[2];   // (1,36,256,256)
    const float* anc = (const float*)d_in[3];   // (589824,4)
    float* out = (float*)d_out;                 // [scores|labels|boxes|keep] = 7000

    k_score<<<NTOT / 256, 256>>>(obj, (const float4*)cls);
    k_scan<<<1, 1024>>>();
    k_collect<<<(NTOT / 4) / 256, 256>>>();
    k_exact<<<CAP / 256, 256>>>(obj);
    k_sort<<<1, 1024>>>(out);
    k_decode<<<(TOPK * 32) / 256, 256>>>(cls, reg, anc, out);
    k_mask<<<TOPK, 1024>>>();
    k_nms<<<1, 32>>>(out);
    (void)in_sizes; (void)n_in; (void)out_size;
}